// round 9
// baseline (speedup 1.0000x reference)
#include <cuda_runtime.h>
#include <math.h>

#define NB 32
#define NS 1024
#define ND 256
#define NDS 64
#define NM 3
#define TS 128   // timesteps per out_kernel block

typedef unsigned long long ull;

// ---------------- scratch (device globals; no cudaMalloc allowed) ----------
__device__ float g_xp[(size_t)NB * NS * NM * NDS];   // [B][S][M*DS]  (XW@x + Xb + Hb)
__device__ float g_hn[(size_t)NB * NS * NM * NDS];   // [B][S][M*DS]  (h_new per step)

// ---------------- packed f32x2 helpers -------------------------------------
__device__ __forceinline__ void fma2(ull& acc, ull a, ull b) {
    asm("fma.rn.f32x2 %0, %1, %2, %0;" : "+l"(acc) : "l"(a), "l"(b));
}
__device__ __forceinline__ ull pack2(float x, float y) {
    ull r; asm("mov.b64 %0, {%1, %2};" : "=l"(r) : "f"(x), "f"(y)); return r;
}
__device__ __forceinline__ float2 unpack2(ull v) {
    float2 r; asm("mov.b64 {%0, %1}, %2;" : "=f"(r.x), "=f"(r.y) : "l"(v)); return r;
}
__device__ __forceinline__ float sum2(ull v) { float2 f = unpack2(v); return f.x + f.y; }

__device__ __forceinline__ float tanh_fast(float x) {
    float y; asm("tanh.approx.f32 %0, %1;" : "=f"(y) : "f"(x)); return y;
}

// ---------------- named barriers --------------------------------------------
__device__ __forceinline__ void bar_sync(int id, int cnt) {
    asm volatile("bar.sync %0, %1;" :: "r"(id), "r"(cnt) : "memory");
}
__device__ __forceinline__ void bar_arrive(int id, int cnt) {
    asm volatile("bar.arrive %0, %1;" :: "r"(id), "r"(cnt) : "memory");
}

// ---------------- cp.async helpers ------------------------------------------
__device__ __forceinline__ void cp_async16(void* smem_dst, const void* gsrc) {
    unsigned s = (unsigned)__cvta_generic_to_shared(smem_dst);
    asm volatile("cp.async.ca.shared.global [%0], [%1], 16;" :: "r"(s), "l"(gsrc));
}
__device__ __forceinline__ void cp_commit() { asm volatile("cp.async.commit_group;"); }
__device__ __forceinline__ void cp_wait1()  { asm volatile("cp.async.wait_group 1;"); }

// ======================= Kernel 1: xp = XW@x + Xb + Hb =====================
// grid (S/64, B, M), block 256 (ty16 x tx16). Output tile: 64 t x 64 d, K=256.
__global__ void __launch_bounds__(256) xproj_kernel(
    const float* __restrict__ xa, const float* __restrict__ xv, const float* __restrict__ xl,
    const float* __restrict__ XW, const float* __restrict__ Xb, const float* __restrict__ Hb)
{
    __shared__ __align__(16) float Xs[64][64];   // [t][k]
    __shared__ __align__(16) float Wt[64][64];   // [k][d] (XW transposed)

    const int m  = blockIdx.z;
    const int bb = blockIdx.y;
    const int t0 = blockIdx.x * 64;
    const float* xm = (m == 0) ? xa : ((m == 1) ? xv : xl);

    const int tid = threadIdx.x;
    const int tx = tid & 15, ty = tid >> 4;

    ull acc[4][2] = {};

    const int ldx_row = tid >> 2, ldx_q = tid & 3;
    const int ldw_d = tid & 63, ldw_g = tid >> 6;

    for (int kc = 0; kc < 4; kc++) {
        __syncthreads();
        #pragma unroll
        for (int g = 0; g < 4; g++) {
            int col = ldx_q * 16 + g * 4;
            float4 v = *(const float4*)&xm[((size_t)(bb * NS) + t0 + ldx_row) * ND + kc * 64 + col];
            *(float4*)&Xs[ldx_row][col] = v;
        }
        #pragma unroll
        for (int g = 0; g < 4; g++) {
            int kk = ldw_g * 16 + g * 4;
            float4 w = *(const float4*)&XW[((size_t)(m * NDS + ldw_d)) * ND + kc * 64 + kk];
            Wt[kk + 0][ldw_d] = w.x; Wt[kk + 1][ldw_d] = w.y;
            Wt[kk + 2][ldw_d] = w.z; Wt[kk + 3][ldw_d] = w.w;
        }
        __syncthreads();
        #pragma unroll 16
        for (int kk = 0; kk < 64; kk++) {
            ull bv0 = *(const ull*)&Wt[kk][2 * tx];
            ull bv1 = *(const ull*)&Wt[kk][2 * tx + 32];
            #pragma unroll
            for (int i = 0; i < 4; i++) {
                float a = Xs[ty + 16 * i][kk];
                ull aa = pack2(a, a);
                fma2(acc[i][0], aa, bv0);
                fma2(acc[i][1], aa, bv1);
            }
        }
    }
    #pragma unroll
    for (int i = 0; i < 4; i++) {
        #pragma unroll
        for (int jp = 0; jp < 2; jp++) {
            int d0 = 2 * tx + 32 * jp;
            float2 v = unpack2(acc[i][jp]);
            float2 xb = *(const float2*)&Xb[m * NDS + d0];
            float2 hb = *(const float2*)&Hb[m * NDS + d0];
            v.x += xb.x + hb.x;
            v.y += xb.y + hb.y;
            *(float2*)&g_xp[((size_t)(bb * NS) + t0 + ty + 16 * i) * (NM * NDS) + m * NDS + d0] = v;
        }
    }
}

// ======================= Kernel 2: warp-specialized sequential scan ========
// grid = 32 (one block per batch element), 512 threads.
//   warps 0-11  (tid 0..383): HW + CW dot group (2 threads per output)
//   warps 12-15 (tid 384..511): gating MLP group (W1 -> tanh -> W2 -> softmax)
// Gating runs concurrently with the dots; they meet at named barrier 2.
__global__ void __launch_bounds__(512, 1) scan_kernel(
    const float* __restrict__ W1, const float* __restrict__ b1,
    const float* __restrict__ W2, const float* __restrict__ b2,
    const float* __restrict__ HW, const float* __restrict__ CW)
{
    __shared__ __align__(16) float sh_h[2][NM * NDS];  // double-buffered state
    __shared__ __align__(16) float sh_part[2][NDS];
    __shared__ __align__(16) float sh_z[NDS];
    __shared__ float sh_raw[12];
    __shared__ float sh_a[12];
    __shared__ __align__(16) float sh_b1[NDS];

    const int u  = threadIdx.x;
    const int bb = blockIdx.x;

    // common preamble: zero h0, stage b1
    if (u < NM * NDS) sh_h[0][u] = 0.0f;
    if (u >= 256 && u < 256 + NDS) sh_b1[u - 256] = b1[u - 256];
    bar_sync(0, 512);

    if (u < 384) {
        // ================= dot group =================
        const int half = u & 1;
        const int o2   = u >> 1;          // 0..191 = m*64+d
        const int m4   = o2 >> 6;
        const int s1 = (m4 == 0) ? 1 : 0;
        const int s2 = (m4 == 2) ? 1 : 2;
        const int src = half ? s2 : s1;

        ull whw[16];   // HW[m4][d4][half*32 .. +32)
        #pragma unroll
        for (int j = 0; j < 16; j++)
            whw[j] = *(const ull*)(HW + (size_t)o2 * NDS + half * 32 + 2 * j);

        ull wcw[32];   // CW[m4][src][d4][0..64)
        #pragma unroll
        for (int j = 0; j < 32; j++)
            wcw[j] = *(const ull*)(CW + ((size_t)((m4 * NM + src) * NDS + (o2 & 63))) * NDS + 2 * j);

        const float* xp_base = g_xp + (size_t)bb * NS * (NM * NDS) + o2;
        float* hn_base = g_hn + (size_t)bb * NS * (NM * NDS) + o2;
        float xp_c = (half == 0) ? __ldg(xp_base) : 0.0f;

        for (int t = 0; t < NS; t++) {
            const int cur = t & 1;
            float xp_n = 0.0f;
            if (half == 0) {
                int tn = (t + 1 < NS) ? (t + 1) : t;
                xp_n = __ldg(xp_base + (size_t)tn * (NM * NDS));
            }
            const float* hm = &sh_h[cur][m4 * 64 + half * 32];
            const float* hs = &sh_h[cur][src * 64];

            ull a0 = 0, a1 = 0, c0 = 0, c1 = 0, c2 = 0, c3 = 0;
            #pragma unroll
            for (int j = 0; j < 8; j++) {
                ulonglong2 hv = *(const ulonglong2*)(hm + 4 * j);
                fma2(a0, hv.x, whw[2 * j]);
                fma2(a1, hv.y, whw[2 * j + 1]);
            }
            #pragma unroll
            for (int j = 0; j < 16; j++) {
                ulonglong2 hv = *(const ulonglong2*)(hs + 4 * j);
                if (j & 1) { fma2(c2, hv.x, wcw[2 * j]); fma2(c3, hv.y, wcw[2 * j + 1]); }
                else       { fma2(c0, hv.x, wcw[2 * j]); fma2(c1, hv.y, wcw[2 * j + 1]); }
            }

            bar_sync(2, 512);   // wait for gating group's attention weights
            float a = sh_a[m4 * 3 + src];
            float val = sum2(a0) + sum2(a1)
                      + a * (sum2(c0) + sum2(c1) + sum2(c2) + sum2(c3));
            val += __shfl_xor_sync(0xffffffffu, val, 1);   // combine halves
            if (half == 0) {
                float su = val + xp_c;
                float hn = su / (1.0f + __expf(-su));       // silu
                sh_h[cur ^ 1][o2] = hn;
                hn_base[(size_t)t * (NM * NDS)] = hn;
                xp_c = xp_n;
            }
            bar_sync(0, 512);   // step end
        }
    } else {
        // ================= gating group =================
        const int ug  = u - 384;          // 0..127
        const int o1  = ug & 63;
        const int seg = ug >> 6;          // 0..1 (96-elem halves of hc)
        const int p   = ug >> 4;          // 0..7 (W2 row)
        const int c   = ug & 15;          // chunk of 4 z elems
        const int r9  = (ug < 9) ? (ug / 3) : 0;
        const int c9  = (ug < 9) ? (ug - 3 * r9) : 0;

        ull w1r[48];   // W1[o1][seg*96 .. +96)
        #pragma unroll
        for (int j = 0; j < 48; j++)
            w1r[j] = *(const ull*)(W1 + (size_t)o1 * (NM * NDS) + seg * 96 + 2 * j);

        ull w2a = *(const ull*)(W2 + (size_t)p * NDS + 4 * c);
        ull w2b = *(const ull*)(W2 + (size_t)p * NDS + 4 * c + 2);
        ull w2c = 0, w2d = 0;
        if (p == 0) {
            w2c = *(const ull*)(W2 + (size_t)8 * NDS + 4 * c);
            w2d = *(const ull*)(W2 + (size_t)8 * NDS + 4 * c + 2);
        }
        const float b2p = b2[p];
        const float b28 = b2[8];

        for (int t = 0; t < NS; t++) {
            const float* hseg = &sh_h[t & 1][seg * 96];
            ull g0 = 0, g1 = 0, g2 = 0, g3 = 0;
            #pragma unroll
            for (int j = 0; j < 24; j++) {
                ulonglong2 hv = *(const ulonglong2*)(hseg + 4 * j);
                if (j & 1) { fma2(g2, hv.x, w1r[2 * j]); fma2(g3, hv.y, w1r[2 * j + 1]); }
                else       { fma2(g0, hv.x, w1r[2 * j]); fma2(g1, hv.y, w1r[2 * j + 1]); }
            }
            sh_part[seg][o1] = sum2(g0) + sum2(g1) + sum2(g2) + sum2(g3);
            bar_sync(3, 128);

            if (ug < NDS)
                sh_z[ug] = tanh_fast(sh_b1[ug] + sh_part[0][ug] + sh_part[1][ug]);
            bar_sync(3, 128);

            // W2: 8 groups of 16 lanes; group 0 also handles row 8
            ulonglong2 zv = *(const ulonglong2*)(sh_z + 4 * c);
            ull pa = 0; fma2(pa, zv.x, w2a); fma2(pa, zv.y, w2b);
            float pr = sum2(pa);
            float pr8 = 0.0f;
            if (p == 0) { ull pb = 0; fma2(pb, zv.x, w2c); fma2(pb, zv.y, w2d); pr8 = sum2(pb); }
            #pragma unroll
            for (int off = 8; off; off >>= 1) {
                pr  += __shfl_xor_sync(0xffffffffu, pr, off);
                pr8 += __shfl_xor_sync(0xffffffffu, pr8, off);
            }
            if (c == 0) {
                sh_raw[p] = pr + b2p;
                if (p == 0) sh_raw[8] = pr8 + b28;
            }
            bar_sync(3, 128);

            if (ug < 9) {
                float r0 = sh_raw[3 * r9], r1 = sh_raw[3 * r9 + 1], r2 = sh_raw[3 * r9 + 2];
                float mx = fmaxf(r0, fmaxf(r1, r2));
                float e0 = __expf(r0 - mx), e1 = __expf(r1 - mx), e2 = __expf(r2 - mx);
                float mine = (c9 == 0) ? e0 : ((c9 == 1) ? e1 : e2);
                sh_a[ug] = (c9 == r9) ? 0.0f : mine / (e0 + e1 + e2);
            }
            bar_arrive(2, 512);  // release attention to the dot group
            bar_sync(0, 512);    // step end
        }
    }
}

// ======================= Kernel 3: y = OW@h_new + Ob; out = LN(y + x) ======
__global__ void __launch_bounds__(256) out_kernel(
    const float* __restrict__ xa, const float* __restrict__ xv, const float* __restrict__ xl,
    const float* __restrict__ OW, const float* __restrict__ Ob,
    const float* __restrict__ lng, const float* __restrict__ lnb,
    float* __restrict__ out)
{
    __shared__ __align__(16) float sh_ht[2][8][NDS];
    __shared__ float sh_red[2][8][2];

    const int tid = threadIdx.x;
    const int t0  = blockIdx.x * TS;
    const int bb  = blockIdx.y;
    const int m   = blockIdx.z;
    const float* xm = (m == 0) ? xa : ((m == 1) ? xv : xl);

    ull ow[32];
    #pragma unroll
    for (int j = 0; j < 32; j++)
        ow[j] = *(const ull*)(OW + ((size_t)m * ND + tid) * NDS + 2 * j);
    const float ob = Ob[m * ND + tid];
    const float gg = lng[m * ND + tid];
    const float be = lnb[m * ND + tid];

    const float* hn_base = g_hn + ((size_t)(bb * NS + t0)) * (NM * NDS) + m * NDS;
    const float* x_base  = xm + ((size_t)bb * NS + t0) * ND;
    float* o_base = out + ((size_t)m * NB + bb) * (size_t)NS * ND + (size_t)t0 * ND;

    const int ptt = tid >> 4;
    const int pq  = tid & 15;

    if (tid < 128) {
        int tc = min(0 * 8 + ptt, TS - 1);
        cp_async16(&sh_ht[0][ptt][pq * 4], hn_base + (size_t)tc * (NM * NDS) + pq * 4);
    }
    cp_commit();

    const int NG = TS / 8;
    for (int g = 0; g < NG; g++) {
        const int buf = g & 1;
        if (tid < 128) {
            int tc = min((g + 1) * 8 + ptt, TS - 1);
            cp_async16(&sh_ht[buf ^ 1][ptt][pq * 4], hn_base + (size_t)tc * (NM * NDS) + pq * 4);
        }
        cp_commit();
        cp_wait1();
        __syncthreads();

        #pragma unroll
        for (int k = 0; k < 8; k++) {
            const int t = g * 8 + k;
            float xval = __ldg(x_base + (size_t)t * ND + tid);

            ull acc = 0;
            #pragma unroll
            for (int j = 0; j < 32; j++)
                fma2(acc, *(const ull*)&sh_ht[buf][k][2 * j], ow[j]);
            float v = sum2(acc) + ob + xval;

            float s = v, ss = v * v;
            #pragma unroll
            for (int off = 16; off; off >>= 1) {
                s  += __shfl_xor_sync(0xffffffffu, s, off);
                ss += __shfl_xor_sync(0xffffffffu, ss, off);
            }
            const int w = tid >> 5, l = tid & 31;
            const int rb = t & 1;
            if (l == 0) { sh_red[rb][w][0] = s; sh_red[rb][w][1] = ss; }
            __syncthreads();
            float S = 0.0f, SS = 0.0f;
            #pragma unroll
            for (int w2 = 0; w2 < 8; w2++) { S += sh_red[rb][w2][0]; SS += sh_red[rb][w2][1]; }
            float mu  = S * (1.0f / 256.0f);
            float var = SS * (1.0f / 256.0f) - mu * mu;
            float r   = rsqrtf(var + 1e-5f);
            o_base[(size_t)t * ND + tid] = (v - mu) * r * gg + be;
        }
    }
}

// =============================== launch ====================================
extern "C" void kernel_launch(void* const* d_in, const int* in_sizes, int n_in,
                              void* d_out, int out_size) {
    const float* xa  = (const float*)d_in[0];
    const float* xv  = (const float*)d_in[1];
    const float* xl  = (const float*)d_in[2];
    const float* XW  = (const float*)d_in[3];
    const float* Xb  = (const float*)d_in[4];
    const float* HW  = (const float*)d_in[5];
    const float* Hb  = (const float*)d_in[6];
    const float* OW  = (const float*)d_in[7];
    const float* Ob  = (const float*)d_in[8];
    const float* CW  = (const float*)d_in[9];
    const float* W1  = (const float*)d_in[10];
    const float* b1  = (const float*)d_in[11];
    const float* W2  = (const float*)d_in[12];
    const float* b2  = (const float*)d_in[13];
    const float* lng = (const float*)d_in[14];
    const float* lnb = (const float*)d_in[15];
    float* out = (float*)d_out;

    dim3 gA(NS / 64, NB, NM);
    xproj_kernel<<<gA, 256>>>(xa, xv, xl, XW, Xb, Hb);

    scan_kernel<<<NB, 512>>>(W1, b1, W2, b2, HW, CW);

    dim3 gC(NS / TS, NB, NM);
    out_kernel<<<gC, 256>>>(xa, xv, xl, OW, Ob, lng, lnb, out);
}